// round 14
// baseline (speedup 1.0000x reference)
#include <cuda_runtime.h>
#include <cuda_fp16.h>
#include <cstdint>

#define BB 32
#define TT 8192
#define DD 256
#define UU 128
#define MT 64
#define NCTA ((BB * TT) / MT)   // 4096 tiles, 128 per batch

// ---- dynamic SMEM layout (bytes); rows padded to 80B (conflict-free) ----
#define A_OFF   0        // 4 x (64 rows x 80B)  = 20480
#define B_OFF   20480    // 4 x (128 rows x 80B) = 40960
#define SC_OFF  61440    // [4][64] floats = 1024
#define ES_OFF  62464    // 64 floats
#define HQ_OFF  62720    // 128 floats
#define B1_OFF  63232    // 128 floats
#define VV_OFF  63744    // 128 floats
#define RED_OFF 64256    // 64 floats
#define SMEM_BYTES 64512

// ---- scratch globals (allocation-free) ----
__device__ float  g_hq[BB * UU];
__device__ __half g_W1h[UU * DD];       // W1 transposed -> [u][d], fp16
__device__ float  g_scores[BB * TT];
__device__ float  g_stats[NCTA * 2];    // per-tile (local max, local expsum)
__device__ float  g_pctx[NCTA * DD];    // per-tile unnormalized partial context
__device__ float  g_bstats[BB * 2];     // per-batch (global max, 1/sum)

// ---------------------------------------------------------------------------
// helpers
// ---------------------------------------------------------------------------
__device__ __forceinline__ uint32_t smem_u32(const void* p) {
    uint32_t a;
    asm("{ .reg .u64 t; cvta.to.shared.u64 t, %1; cvt.u32.u64 %0, t; }" : "=r"(a) : "l"(p));
    return a;
}
__device__ __forceinline__ void ldsm4p(uint32_t* r, uint32_t addr) {
    asm volatile("ldmatrix.sync.aligned.m8n8.x4.shared.b16 {%0,%1,%2,%3}, [%4];"
                 : "=r"(r[0]), "=r"(r[1]), "=r"(r[2]), "=r"(r[3]) : "r"(addr));
}
__device__ __forceinline__ void mma_f16(float c[4],
                                        uint32_t a0, uint32_t a1, uint32_t a2, uint32_t a3,
                                        uint32_t b0, uint32_t b1) {
    asm("mma.sync.aligned.m16n8k16.row.col.f32.f16.f16.f32 "
        "{%0,%1,%2,%3}, {%4,%5,%6,%7}, {%8,%9}, {%0,%1,%2,%3};"
        : "+f"(c[0]), "+f"(c[1]), "+f"(c[2]), "+f"(c[3])
        : "r"(a0), "r"(a1), "r"(a2), "r"(a3), "r"(b0), "r"(b1));
}
__device__ __forceinline__ void cp16(uint32_t dst, const void* src) {
    asm volatile("cp.async.cg.shared.global [%0], [%1], 16;"
                 :: "r"(dst), "l"(src) : "memory");
}
__device__ __forceinline__ void cp_commit() {
    asm volatile("cp.async.commit_group;" ::: "memory");
}
__device__ __forceinline__ void cp_wait0() {
    asm volatile("cp.async.wait_group 0;" ::: "memory");
}
__device__ __forceinline__ uint32_t h2_bits(__half2 h) {
    union { __half2 h; uint32_t u; } cvt;
    cvt.h = h;
    return cvt.u;
}
__device__ __forceinline__ float tanh_fast(float x) {   // 1 MUFU, ~5e-4 abs err
    float y;
    asm("tanh.approx.f32 %0, %1;" : "=f"(y) : "f"(x));
    return y;
}

// ---------------------------------------------------------------------------
// fused prep: blocks 0..31 -> hq, blocks 32..159 -> W1 transpose+fp16
// ---------------------------------------------------------------------------
__global__ void prep_kernel(const float* __restrict__ query,
                            const float* __restrict__ W2,
                            const float* __restrict__ W2b,
                            const float* __restrict__ W1) {
    if (blockIdx.x < 32) {
        if (threadIdx.x < UU) {
            int b = blockIdx.x, u = threadIdx.x;
            const float* q = query + b * DD;
            float acc = 0.0f;
#pragma unroll 8
            for (int d = 0; d < DD; d++) acc += q[d] * W2[d * UU + u];
            g_hq[b * UU + u] = fmaxf(acc + W2b[u], 0.0f);
        }
    } else {
        int u = blockIdx.x - 32, d = threadIdx.x;
        g_W1h[u * DD + d] = __float2half_rn(W1[d * UU + u]);
    }
}

// ---------------------------------------------------------------------------
// scores: MT=64 tile, 8 warps of 32x32, 3 CTAs/SM.  fused local softmax +
// partial context (values re-read, L2-hot fp32).
// ---------------------------------------------------------------------------
__global__ __launch_bounds__(256, 3)
void scores_kernel(const float* __restrict__ values,
                   const float* __restrict__ W1b,
                   const float* __restrict__ Vk,
                   const float* __restrict__ Vb) {
    extern __shared__ char smem[];
    const uint32_t sbase = smem_u32(smem);
    const int tid  = threadIdx.x;
    const int wid  = tid >> 5;
    const int lane = tid & 31;
    const int rg   = wid >> 2;        // 0..1: rows [32*rg, +32)
    const int ch   = wid & 3;         // 0..3: cols [32*ch, +32)
    const int mrow = lane & 7;
    const int mi   = lane >> 3;
    const int tg   = lane & 3;
    const int g    = lane >> 2;
    const int tile = blockIdx.x;
    const int row0 = tile * MT;
    const int b    = tile >> 7;       // 128 tiles per batch

    float* s_sc = (float*)(smem + SC_OFF);
    float* s_es = (float*)(smem + ES_OFF);
    float* s_hq = (float*)(smem + HQ_OFF);
    float* s_b1 = (float*)(smem + B1_OFF);
    float* s_v  = (float*)(smem + VV_OFF);
    float* s_rd = (float*)(smem + RED_OFF);

    if (tid < UU) {
        s_hq[tid] = g_hq[b * UU + tid];
        s_b1[tid] = W1b[tid];
        s_v[tid]  = Vk[tid];
    }

    // ---- B staging via cp.async (fp16, 4-buffer ring) ----
    auto stageB = [&](int c) {
        const uint32_t base = sbase + B_OFF + (c & 3) * 10240;
        const __half* src0 = g_W1h + c * 32;
#pragma unroll
        for (int i = 0; i < 2; i++) {
            int idx = tid + i * 256;          // 512 x 16B = 128 rows x 32 halves
            int u = idx >> 2, kk = idx & 3;
            cp16(base + u * 80 + kk * 16, src0 + u * DD + kk * 8);
        }
    };

    // ---- A staging: LDG fp32 -> cvt fp16 -> STS (4-buffer ring) ----
    const int ar = tid >> 2;                  // row 0..63
    const int ac = tid & 3;                   // 16B column unit
    uint4 avh[2];
    auto ldgA = [&](int c, int s) {
        const float* s0 = values + (size_t)(row0 + ar) * DD + c * 32 + ac * 8;
        float4 v0 = *(const float4*)s0;
        float4 v1 = *(const float4*)(s0 + 4);
        avh[s] = make_uint4(h2_bits(__floats2half2_rn(v0.x, v0.y)),
                            h2_bits(__floats2half2_rn(v0.z, v0.w)),
                            h2_bits(__floats2half2_rn(v1.x, v1.y)),
                            h2_bits(__floats2half2_rn(v1.z, v1.w)));
    };
    auto stsA = [&](int c, int s) {
        *(uint4*)(smem + A_OFF + (c & 3) * 5120 + ar * 80 + ac * 16) = avh[s];
    };

    // fragment address components
    const int a_r  = 32 * rg + mrow + 8 * (mi & 1);
    const int a_kb = (mi >> 1) * 16;
    const int b_n  = 32 * ch + mrow + 8 * (mi >> 1);
    const int b_kb = (mi & 1) * 16;

    // ---- preamble ----
    stageB(0); stageB(1); cp_commit();
    ldgA(0, 0); ldgA(1, 1);
    stsA(0, 0); stsA(1, 1);
    ldgA(2, 0);
    cp_wait0();
    __syncthreads();

    float acc[2][4][4];
#pragma unroll
    for (int m = 0; m < 2; m++)
#pragma unroll
        for (int j = 0; j < 4; j++)
#pragma unroll
            for (int q = 0; q < 4; q++) acc[m][j][q] = 0.0f;

    // ---- mainloop: 4 its x 2 chunks x 2 q-steps ----
#pragma unroll
    for (int it = 0; it < 4; it++) {
        const int c0 = 2 * it;
        if (it < 3) { stageB(c0 + 2); stageB(c0 + 3); cp_commit(); }
#pragma unroll
        for (int half = 0; half < 2; half++) {
            const int c = c0 + half;
            const uint32_t abase = sbase + A_OFF + (c & 3) * 5120;
            const uint32_t bbase = sbase + B_OFF + (c & 3) * 10240;
#pragma unroll
            for (int qq = 0; qq < 2; qq++) {
                const int k0 = qq * 32;
                uint32_t afr[8], bfr[8];
                ldsm4p(afr,     abase + (a_r)      * 80 + a_kb + k0);
                ldsm4p(afr + 4, abase + (a_r + 16) * 80 + a_kb + k0);
                ldsm4p(bfr,     bbase + (b_n)      * 80 + b_kb + k0);
                ldsm4p(bfr + 4, bbase + (b_n + 16) * 80 + b_kb + k0);
                mma_f16(acc[0][0], afr[0], afr[1], afr[2], afr[3], bfr[0], bfr[1]);
                mma_f16(acc[0][1], afr[0], afr[1], afr[2], afr[3], bfr[2], bfr[3]);
                mma_f16(acc[0][2], afr[0], afr[1], afr[2], afr[3], bfr[4], bfr[5]);
                mma_f16(acc[0][3], afr[0], afr[1], afr[2], afr[3], bfr[6], bfr[7]);
                mma_f16(acc[1][0], afr[4], afr[5], afr[6], afr[7], bfr[0], bfr[1]);
                mma_f16(acc[1][1], afr[4], afr[5], afr[6], afr[7], bfr[2], bfr[3]);
                mma_f16(acc[1][2], afr[4], afr[5], afr[6], afr[7], bfr[4], bfr[5]);
                mma_f16(acc[1][3], afr[4], afr[5], afr[6], afr[7], bfr[6], bfr[7]);
            }
            if (half == 0) {
                if (it < 3) { stsA(c0 + 2, 0); ldgA(c0 + 3, 1); }
            } else {
                if (it < 2)       { stsA(c0 + 3, 1); ldgA(c0 + 4, 0); }
                else if (it == 2) { stsA(7, 1); }
            }
        }
        if (it < 3) cp_wait0();
        __syncthreads();
    }

    // ---- epilogue 1: per-row score partials (this warp's 32-col slice) ----
    float s[4] = {0.f, 0.f, 0.f, 0.f};
#pragma unroll
    for (int j = 0; j < 4; j++) {
        const int u0 = 32 * ch + 8 * j + 2 * tg;
        const int u1 = u0 + 1;
        const float v0 = s_v[u0], v1 = s_v[u1];
        const float h0 = s_hq[u0], h1 = s_hq[u1];
        const float c0 = s_b1[u0], c1 = s_b1[u1];
#pragma unroll
        for (int m = 0; m < 2; m++) {
            s[2 * m]     += v0 * tanh_fast(fmaxf(acc[m][j][0] + c0, 0.f) + h0)
                          + v1 * tanh_fast(fmaxf(acc[m][j][1] + c1, 0.f) + h1);
            s[2 * m + 1] += v0 * tanh_fast(fmaxf(acc[m][j][2] + c0, 0.f) + h0)
                          + v1 * tanh_fast(fmaxf(acc[m][j][3] + c1, 0.f) + h1);
        }
    }
#pragma unroll
    for (int i = 0; i < 4; i++) {
        s[i] += __shfl_xor_sync(0xffffffffu, s[i], 1);
        s[i] += __shfl_xor_sync(0xffffffffu, s[i], 2);
    }
    if (tg == 0) {
        const int rb = 32 * rg + g;
        s_sc[ch * 64 + rb]      = s[0];
        s_sc[ch * 64 + rb + 8]  = s[1];
        s_sc[ch * 64 + rb + 16] = s[2];
        s_sc[ch * 64 + rb + 24] = s[3];
    }
    __syncthreads();

    // ---- epilogue 2: combine 4 col slices, local max / exp / sum ----
    float myv = -3.0e38f;
    if (tid < 64) {
        myv = s_sc[tid] + s_sc[64 + tid] + s_sc[128 + tid] + s_sc[192 + tid] + Vb[0];
        g_scores[row0 + tid] = myv;
    }
    float m = myv;
#pragma unroll
    for (int o = 16; o > 0; o >>= 1) m = fmaxf(m, __shfl_xor_sync(0xffffffffu, m, o));
    if (lane == 0 && wid < 2) s_rd[wid] = m;
    __syncthreads();
    if (tid == 0) s_rd[8] = fmaxf(s_rd[0], s_rd[1]);
    __syncthreads();
    const float mloc = s_rd[8];
    float e = (tid < 64) ? __expf(myv - mloc) : 0.0f;
    if (tid < 64) s_es[tid] = e;
    float sum = e;
#pragma unroll
    for (int o = 16; o > 0; o >>= 1) sum += __shfl_xor_sync(0xffffffffu, sum, o);
    if (lane == 0 && wid < 2) s_rd[2 + wid] = sum;
    __syncthreads();
    if (tid == 0) {
        g_stats[tile * 2]     = mloc;
        g_stats[tile * 2 + 1] = s_rd[2] + s_rd[3];
    }
    __syncthreads();

    // ---- epilogue 3: partial context, exact fp32 values (L2-hot tile) ----
    {
        float a = 0.0f;
#pragma unroll 8
        for (int r = 0; r < MT; r++)
            a += s_es[r] * values[(size_t)(row0 + r) * DD + tid];
        g_pctx[tile * DD + tid] = a;
    }
}

// ---------------------------------------------------------------------------
// per-batch rescale + context reduction (128 partials per batch), parallel
// ---------------------------------------------------------------------------
__global__ void reduce_kernel(float* __restrict__ ctx) {
    __shared__ float coef[128], red[16];
    const int b = blockIdx.x, tid = threadIdx.x, lane = tid & 31, w = tid >> 5;
    float val = 0.0f, cs = 0.0f;
    float m = -3.0e38f;
    if (tid < 128) {
        val = g_stats[(b * 128 + tid) * 2];
        cs  = g_stats[(b * 128 + tid) * 2 + 1];
        m = val;
    }
#pragma unroll
    for (int o = 16; o > 0; o >>= 1) m = fmaxf(m, __shfl_xor_sync(0xffffffffu, m, o));
    if (tid < 128 && lane == 0) red[w] = m;
    __syncthreads();
    if (tid == 0)
        red[8] = fmaxf(fmaxf(red[0], red[1]), fmaxf(red[2], red[3]));
    __syncthreads();
    const float M = red[8];
    float c = 0.0f;
    if (tid < 128) {
        c = __expf(val - M);
        coef[tid] = c;
        c *= cs;
    }
#pragma unroll
    for (int o = 16; o > 0; o >>= 1) c += __shfl_xor_sync(0xffffffffu, c, o);
    if (tid < 128 && lane == 0) red[4 + w] = c;
    __syncthreads();
    if (tid == 0) {
        float S = red[4] + red[5] + red[6] + red[7];
        red[9] = 1.0f / S;
        g_bstats[b * 2] = M;
        g_bstats[b * 2 + 1] = 1.0f / S;
    }
    __syncthreads();
    const float inv = red[9];
    float acc = 0.0f;
#pragma unroll 8
    for (int k = 0; k < 128; k++) acc += coef[k] * g_pctx[(b * 128 + k) * DD + tid];
    ctx[b * DD + tid] = acc * inv;
}

// normalized attention weights (float4-vectorized)
__global__ void weights_kernel(float* __restrict__ w) {
    int i = blockIdx.x * 256 + threadIdx.x;      // float4 index; 65536 total
    int b = i >> 11;                             // 2048 float4 per batch
    float4 sc = ((const float4*)g_scores)[i];
    const float M = g_bstats[b * 2];
    const float inv = g_bstats[b * 2 + 1];
    float4 o;
    o.x = __expf(sc.x - M) * inv;
    o.y = __expf(sc.y - M) * inv;
    o.z = __expf(sc.z - M) * inv;
    o.w = __expf(sc.w - M) * inv;
    ((float4*)w)[i] = o;
}

// ---------------------------------------------------------------------------
extern "C" void kernel_launch(void* const* d_in, const int* in_sizes, int n_in,
                              void* d_out, int out_size) {
    const float* query  = (const float*)d_in[0];
    const float* values = (const float*)d_in[1];
    const float* W1     = (const float*)d_in[2];
    const float* W1b    = (const float*)d_in[3];
    const float* W2     = (const float*)d_in[4];
    const float* W2b    = (const float*)d_in[5];
    const float* Vk     = (const float*)d_in[6];
    const float* Vb     = (const float*)d_in[7];

    float* out = (float*)d_out;
    float* ctx = out;               // [B, D]
    float* wts = out + BB * DD;     // [B, T, 1]

    static bool attr_set = false;
    if (!attr_set) {
        cudaFuncSetAttribute(scores_kernel, cudaFuncAttributeMaxDynamicSharedMemorySize,
                             SMEM_BYTES);
        attr_set = true;
    }

    prep_kernel<<<160, 256>>>(query, W2, W2b, W1);
    scores_kernel<<<NCTA, 256, SMEM_BYTES>>>(values, W1b, Vk, Vb);
    reduce_kernel<<<BB, 256>>>(ctx);
    weights_kernel<<<256, 256>>>(wts);
}

// round 15
// speedup vs baseline: 1.0691x; 1.0691x over previous
#include <cuda_runtime.h>
#include <cuda_fp16.h>
#include <cstdint>

#define BB 32
#define TT 8192
#define DD 256
#define UU 128
#define MT 128
#define NCTA ((BB * TT) / MT)   // 2048 tiles, 64 per batch
#define THREADS 512

// ---- dynamic SMEM layout (bytes); rows padded to 80B (conflict-free) ----
#define A_OFF   0        // 4 x (128 rows x 80B) = 40960 (fp16 ring)
#define B_OFF   40960    // 4 x (128 rows x 80B) = 40960
#define SC_OFF  81920    // [2][128] floats = 1024
#define ES_OFF  82944    // 128 floats = 512
#define HQ_OFF  83456    // 128 floats
#define B1_OFF  83968    // 128 floats
#define VV_OFF  84480    // 128 floats
#define RED_OFF 84992    // 64 floats = 256
#define PC_OFF  85248    // [2][256] floats = 2048
#define SMEM_BYTES 87296

// ---- scratch globals (allocation-free) ----
__device__ float  g_hq[BB * UU];
__device__ __half g_W1h[UU * DD];       // W1 transposed -> [u][d], fp16
__device__ float  g_scores[BB * TT];
__device__ float  g_stats[NCTA * 2];    // per-tile (local max, local expsum)
__device__ float  g_pctx[NCTA * DD];    // per-tile unnormalized partial context
__device__ float  g_bstats[BB * 2];     // per-batch (global max, 1/sum)

// ---------------------------------------------------------------------------
// helpers
// ---------------------------------------------------------------------------
__device__ __forceinline__ uint32_t smem_u32(const void* p) {
    uint32_t a;
    asm("{ .reg .u64 t; cvta.to.shared.u64 t, %1; cvt.u32.u64 %0, t; }" : "=r"(a) : "l"(p));
    return a;
}
__device__ __forceinline__ void ldsm4p(uint32_t* r, uint32_t addr) {
    asm volatile("ldmatrix.sync.aligned.m8n8.x4.shared.b16 {%0,%1,%2,%3}, [%4];"
                 : "=r"(r[0]), "=r"(r[1]), "=r"(r[2]), "=r"(r[3]) : "r"(addr));
}
__device__ __forceinline__ void mma_f16(float c[4],
                                        uint32_t a0, uint32_t a1, uint32_t a2, uint32_t a3,
                                        uint32_t b0, uint32_t b1) {
    asm("mma.sync.aligned.m16n8k16.row.col.f32.f16.f16.f32 "
        "{%0,%1,%2,%3}, {%4,%5,%6,%7}, {%8,%9}, {%0,%1,%2,%3};"
        : "+f"(c[0]), "+f"(c[1]), "+f"(c[2]), "+f"(c[3])
        : "r"(a0), "r"(a1), "r"(a2), "r"(a3), "r"(b0), "r"(b1));
}
__device__ __forceinline__ void cp16(uint32_t dst, const void* src) {
    asm volatile("cp.async.cg.shared.global [%0], [%1], 16;"
                 :: "r"(dst), "l"(src) : "memory");
}
__device__ __forceinline__ void cp_commit() {
    asm volatile("cp.async.commit_group;" ::: "memory");
}
__device__ __forceinline__ void cp_wait0() {
    asm volatile("cp.async.wait_group 0;" ::: "memory");
}
__device__ __forceinline__ uint32_t h2_bits(__half2 h) {
    union { __half2 h; uint32_t u; } cvt;
    cvt.h = h;
    return cvt.u;
}
__device__ __forceinline__ float tanh_fast(float x) {   // 1 MUFU, ~5e-4 abs err
    float y;
    asm("tanh.approx.f32 %0, %1;" : "=f"(y) : "f"(x));
    return y;
}

// ---------------------------------------------------------------------------
// fused prep: blocks 0..31 -> hq, blocks 32..159 -> W1 transpose+fp16
// ---------------------------------------------------------------------------
__global__ void prep_kernel(const float* __restrict__ query,
                            const float* __restrict__ W2,
                            const float* __restrict__ W2b,
                            const float* __restrict__ W1) {
    if (blockIdx.x < 32) {
        if (threadIdx.x < UU) {
            int b = blockIdx.x, u = threadIdx.x;
            const float* q = query + b * DD;
            float acc = 0.0f;
#pragma unroll 8
            for (int d = 0; d < DD; d++) acc += q[d] * W2[d * UU + u];
            g_hq[b * UU + u] = fmaxf(acc + W2b[u], 0.0f);
        }
    } else {
        int u = blockIdx.x - 32, d = threadIdx.x;
        g_W1h[u * DD + d] = __float2half_rn(W1[d * UU + u]);
    }
}

// ---------------------------------------------------------------------------
// scores: MT=128, 512 threads, 16 warps of 16x64, 2 CTAs/SM = 32 warps/SM.
// fp16 mma, 4-deep A/B rings, deep LDG lookahead.  fused local softmax +
// partial context (exact fp32 values, L2-hot).
// ---------------------------------------------------------------------------
__global__ __launch_bounds__(THREADS, 2)
void scores_kernel(const float* __restrict__ values,
                   const float* __restrict__ W1b,
                   const float* __restrict__ Vk,
                   const float* __restrict__ Vb) {
    extern __shared__ char smem[];
    const uint32_t sbase = smem_u32(smem);
    const int tid  = threadIdx.x;
    const int wid  = tid >> 5;
    const int lane = tid & 31;
    const int rg   = wid >> 1;        // 0..7: rows [16*rg, +16)
    const int ch   = wid & 1;         // 0..1: cols [64*ch, +64)
    const int mrow = lane & 7;
    const int mi   = lane >> 3;
    const int tg   = lane & 3;
    const int g    = lane >> 2;
    const int tile = blockIdx.x;
    const int row0 = tile * MT;
    const int b    = tile >> 6;       // 64 tiles per batch

    float* s_sc = (float*)(smem + SC_OFF);
    float* s_es = (float*)(smem + ES_OFF);
    float* s_hq = (float*)(smem + HQ_OFF);
    float* s_b1 = (float*)(smem + B1_OFF);
    float* s_v  = (float*)(smem + VV_OFF);
    float* s_rd = (float*)(smem + RED_OFF);
    float* s_pc = (float*)(smem + PC_OFF);

    if (tid < UU) {
        s_hq[tid] = g_hq[b * UU + tid];
        s_b1[tid] = W1b[tid];
        s_v[tid]  = Vk[tid];
    }

    // ---- B staging via cp.async (fp16, 4-buffer ring); 1 cp16/thread ----
    auto stageB = [&](int c) {
        const uint32_t base = sbase + B_OFF + (c & 3) * 10240;
        const int u = tid >> 2, kk = tid & 3;   // 512 x 16B = 128 rows x 32 halves
        cp16(base + u * 80 + kk * 16, g_W1h + c * 32 + u * DD + kk * 8);
    };

    // ---- A staging: LDG fp32 -> cvt fp16 -> STS into 4-ring; 2 reg sets ----
    const int ar = tid >> 2;                  // row 0..127
    const int ac = tid & 3;                   // 8-float column unit
    uint4 avh[2];
    auto ldgA = [&](int c, int s) {
        const float* s0 = values + (size_t)(row0 + ar) * DD + c * 32 + ac * 8;
        float4 v0 = *(const float4*)s0;
        float4 v1 = *(const float4*)(s0 + 4);
        avh[s] = make_uint4(h2_bits(__floats2half2_rn(v0.x, v0.y)),
                            h2_bits(__floats2half2_rn(v0.z, v0.w)),
                            h2_bits(__floats2half2_rn(v1.x, v1.y)),
                            h2_bits(__floats2half2_rn(v1.z, v1.w)));
    };
    auto stsA = [&](int c, int s) {
        *(uint4*)(smem + A_OFF + (c & 3) * 10240 + ar * 80 + ac * 16) = avh[s];
    };

    // fragment address components
    const int a_r  = 16 * rg + mrow + 8 * (mi & 1);
    const int a_kb = (mi >> 1) * 16;
    const int b_n  = 64 * ch + mrow + 8 * (mi >> 1);
    const int b_kb = (mi & 1) * 16;

    // ---- preamble: B(0,1) async; A chunks 0,1 staged, 2,3 in flight ----
    stageB(0); stageB(1); cp_commit();
    ldgA(0, 0); ldgA(1, 1);
    stsA(0, 0); ldgA(2, 0);
    stsA(1, 1); ldgA(3, 1);
    cp_wait0();
    __syncthreads();

    float acc[8][4];
#pragma unroll
    for (int j = 0; j < 8; j++)
#pragma unroll
        for (int q = 0; q < 4; q++) acc[j][q] = 0.0f;

    // ---- mainloop: 4 its x (2 chunks x 2 q-steps) ----
#pragma unroll
    for (int it = 0; it < 4; it++) {
        const int c0 = 2 * it;
        if (it < 3) { stageB(c0 + 2); stageB(c0 + 3); cp_commit(); }
#pragma unroll
        for (int half = 0; half < 2; half++) {
            const int c = c0 + half;
            const uint32_t abase = sbase + A_OFF + (c & 3) * 10240;
            const uint32_t bbase = sbase + B_OFF + (c & 3) * 10240;
#pragma unroll
            for (int qq = 0; qq < 2; qq++) {
                const int k0 = qq * 32;
                uint32_t afr[4], bf0[4], bf1[4];
                ldsm4p(afr, abase + a_r * 80 + a_kb + k0);
                ldsm4p(bf0, bbase + (b_n)      * 80 + b_kb + k0);
                ldsm4p(bf1, bbase + (b_n + 16) * 80 + b_kb + k0);
                mma_f16(acc[0], afr[0], afr[1], afr[2], afr[3], bf0[0], bf0[1]);
                mma_f16(acc[1], afr[0], afr[1], afr[2], afr[3], bf0[2], bf0[3]);
                mma_f16(acc[2], afr[0], afr[1], afr[2], afr[3], bf1[0], bf1[1]);
                mma_f16(acc[3], afr[0], afr[1], afr[2], afr[3], bf1[2], bf1[3]);
                ldsm4p(bf0, bbase + (b_n + 32) * 80 + b_kb + k0);
                ldsm4p(bf1, bbase + (b_n + 48) * 80 + b_kb + k0);
                mma_f16(acc[4], afr[0], afr[1], afr[2], afr[3], bf0[0], bf0[1]);
                mma_f16(acc[5], afr[0], afr[1], afr[2], afr[3], bf0[2], bf0[3]);
                mma_f16(acc[6], afr[0], afr[1], afr[2], afr[3], bf1[0], bf1[1]);
                mma_f16(acc[7], afr[0], afr[1], afr[2], afr[3], bf1[2], bf1[3]);
            }
            if (half == 0) {
                if (it < 3) stsA(c0 + 2, 0);
                if (it < 2) ldgA(c0 + 4, 0);
            } else {
                if (it < 3) stsA(c0 + 3, 1);
                if (it < 2) ldgA(c0 + 5, 1);
            }
        }
        if (it < 3) cp_wait0();
        __syncthreads();
    }

    // ---- epilogue 1: per-row score partials (warp's 16 rows x 64 cols) ----
    float s0 = 0.f, s1 = 0.f;
#pragma unroll
    for (int j = 0; j < 8; j++) {
        const int u0 = 64 * ch + 8 * j + 2 * tg;
        const int u1 = u0 + 1;
        const float v0 = s_v[u0], v1 = s_v[u1];
        const float h0 = s_hq[u0], h1 = s_hq[u1];
        const float c0 = s_b1[u0], c1 = s_b1[u1];
        s0 += v0 * tanh_fast(fmaxf(acc[j][0] + c0, 0.f) + h0)
            + v1 * tanh_fast(fmaxf(acc[j][1] + c1, 0.f) + h1);
        s1 += v0 * tanh_fast(fmaxf(acc[j][2] + c0, 0.f) + h0)
            + v1 * tanh_fast(fmaxf(acc[j][3] + c1, 0.f) + h1);
    }
    s0 += __shfl_xor_sync(0xffffffffu, s0, 1);
    s0 += __shfl_xor_sync(0xffffffffu, s0, 2);
    s1 += __shfl_xor_sync(0xffffffffu, s1, 1);
    s1 += __shfl_xor_sync(0xffffffffu, s1, 2);
    if (tg == 0) {
        const int rb = 16 * rg + g;
        s_sc[ch * 128 + rb]     = s0;
        s_sc[ch * 128 + rb + 8] = s1;
    }
    __syncthreads();

    // ---- epilogue 2: combine halves, local max / exp / sum ----
    float myv = -3.0e38f;
    if (tid < 128) {
        myv = s_sc[tid] + s_sc[128 + tid] + Vb[0];
        g_scores[row0 + tid] = myv;
    }
    float m = myv;
#pragma unroll
    for (int o = 16; o > 0; o >>= 1) m = fmaxf(m, __shfl_xor_sync(0xffffffffu, m, o));
    if (lane == 0 && wid < 4) s_rd[wid] = m;
    __syncthreads();
    if (tid == 0)
        s_rd[8] = fmaxf(fmaxf(s_rd[0], s_rd[1]), fmaxf(s_rd[2], s_rd[3]));
    __syncthreads();
    const float mloc = s_rd[8];
    float e = (tid < 128) ? __expf(myv - mloc) : 0.0f;
    if (tid < 128) s_es[tid] = e;
    float sum = e;
#pragma unroll
    for (int o = 16; o > 0; o >>= 1) sum += __shfl_xor_sync(0xffffffffu, sum, o);
    if (lane == 0 && wid < 4) s_rd[4 + wid] = sum;
    __syncthreads();
    if (tid == 0) {
        g_stats[tile * 2]     = mloc;
        g_stats[tile * 2 + 1] = s_rd[4] + s_rd[5] + s_rd[6] + s_rd[7];
    }
    __syncthreads();

    // ---- epilogue 3: partial context, exact fp32 (L2-hot), 512 threads ----
    {
        const int d = tid & 255, h = tid >> 8;   // h=0,1: row halves
        const float* vp = values + (size_t)(row0 + h * 64) * DD + d;
        const float* ep = s_es + h * 64;
        float a = 0.0f;
#pragma unroll 16
        for (int r = 0; r < 64; r++) a += ep[r] * vp[(size_t)r * DD];
        s_pc[h * 256 + d] = a;
    }
    __syncthreads();
    if (tid < 256) g_pctx[tile * DD + tid] = s_pc[tid] + s_pc[256 + tid];
}

// ---------------------------------------------------------------------------
// per-batch rescale + context reduction (64 partials per batch), parallel
// ---------------------------------------------------------------------------
__global__ void reduce_kernel(float* __restrict__ ctx) {
    __shared__ float coef[64], red[8];
    const int b = blockIdx.x, tid = threadIdx.x, lane = tid & 31, w = tid >> 5;
    float val = 0.0f, cs = 0.0f;
    float m = -3.0e38f;
    if (tid < 64) {
        val = g_stats[(b * 64 + tid) * 2];
        cs  = g_stats[(b * 64 + tid) * 2 + 1];
        m = val;
    }
#pragma unroll
    for (int o = 16; o > 0; o >>= 1) m = fmaxf(m, __shfl_xor_sync(0xffffffffu, m, o));
    if (tid < 64 && lane == 0) red[w] = m;
    __syncthreads();
    if (tid == 0) red[2] = fmaxf(red[0], red[1]);
    __syncthreads();
    const float M = red[2];
    float c = 0.0f;
    if (tid < 64) {
        c = __expf(val - M);
        coef[tid] = c;
        c *= cs;
    }
#pragma unroll
    for (int o = 16; o > 0; o >>= 1) c += __shfl_xor_sync(0xffffffffu, c, o);
    if (tid < 64 && lane == 0) red[4 + w] = c;
    __syncthreads();
    if (tid == 0) {
        float S = red[4] + red[5];
        red[6] = 1.0f / S;
        g_bstats[b * 2] = M;
        g_bstats[b * 2 + 1] = 1.0f / S;
    }
    __syncthreads();
    const float inv = red[6];
    float acc = 0.0f;
#pragma unroll
    for (int k = 0; k < 64; k++) acc += coef[k] * g_pctx[(b * 64 + k) * DD + tid];
    ctx[b * DD + tid] = acc * inv;
}

// normalized attention weights (float4-vectorized)
__global__ void weights_kernel(float* __restrict__ w) {
    int i = blockIdx.x * 256 + threadIdx.x;      // float4 index; 65536 total
    int b = i >> 11;                             // 2048 float4 per batch
    float4 sc = ((const float4*)g_scores)[i];
    const float M = g_bstats[b * 2];
    const float inv = g_bstats[b * 2 + 1];
    float4 o;
    o.x = __expf(sc.x - M) * inv;
    o.y = __expf(sc.y - M) * inv;
    o.z = __expf(sc.z - M) * inv;
    o.w = __expf(sc.w - M) * inv;
    ((float4*)w)[i] = o;
}

// ---------------------------------------------------------------------------
extern "C" void kernel_launch(void* const* d_in, const int* in_sizes, int n_in,
                              void* d_out, int out_size) {
    const float* query  = (const float*)d_in[0];
    const float* values = (const float*)d_in[1];
    const float* W1     = (const float*)d_in[2];
    const float* W1b    = (const float*)d_in[3];
    const float* W2     = (const float*)d_in[4];
    const float* W2b    = (const float*)d_in[5];
    const float* Vk     = (const float*)d_in[6];
    const float* Vb     = (const float*)d_in[7];

    float* out = (float*)d_out;
    float* ctx = out;               // [B, D]
    float* wts = out + BB * DD;     // [B, T, 1]

    static bool attr_set = false;
    if (!attr_set) {
        cudaFuncSetAttribute(scores_kernel, cudaFuncAttributeMaxDynamicSharedMemorySize,
                             SMEM_BYTES);
        attr_set = true;
    }

    prep_kernel<<<160, 256>>>(query, W2, W2b, W1);
    scores_kernel<<<NCTA, THREADS, SMEM_BYTES>>>(values, W1b, Vk, Vb);
    reduce_kernel<<<BB, 256>>>(ctx);
    weights_kernel<<<256, 256>>>(wts);
}

// round 16
// speedup vs baseline: 1.0850x; 1.0149x over previous
#include <cuda_runtime.h>
#include <cuda_fp16.h>
#include <cstdint>

#define BB 32
#define TT 8192
#define DD 256
#define UU 128
#define MT 128
#define NCTA ((BB * TT) / MT)   // 2048 tiles, 64 per batch

#define AROW 528                 // A row stride BYTES: 512 payload + 16 pad
// ---- dynamic SMEM layout (bytes) ----
#define A_OFF   0                // 128 rows x 528B = 67584 (full fp16 tile)
#define B_OFF   67584            // 4 x (128 rows x 80B) = 40960
#define SC_OFF  108544           // [2][128] floats = 1024
#define ES_OFF  109568           // 128 floats
#define HQ_OFF  110080           // 128 floats
#define B1_OFF  110592           // 128 floats
#define VV_OFF  111104           // 128 floats
#define RED_OFF 111616           // 64 floats
#define SMEM_BYTES 112128

// ---- scratch globals (allocation-free) ----
__device__ float  g_hq[BB * UU];
__device__ __half g_W1h[UU * DD];       // W1 transposed -> [u][d], fp16
__device__ float  g_scores[BB * TT];
__device__ float  g_stats[NCTA * 2];    // per-tile (local max, local expsum)
__device__ float  g_pctx[NCTA * DD];    // per-tile unnormalized partial context

// ---------------------------------------------------------------------------
// helpers
// ---------------------------------------------------------------------------
__device__ __forceinline__ uint32_t smem_u32(const void* p) {
    uint32_t a;
    asm("{ .reg .u64 t; cvta.to.shared.u64 t, %1; cvt.u32.u64 %0, t; }" : "=r"(a) : "l"(p));
    return a;
}
__device__ __forceinline__ void ldsm4(uint32_t (&r)[4], uint32_t addr) {
    asm volatile("ldmatrix.sync.aligned.m8n8.x4.shared.b16 {%0,%1,%2,%3}, [%4];"
                 : "=r"(r[0]), "=r"(r[1]), "=r"(r[2]), "=r"(r[3]) : "r"(addr));
}
__device__ __forceinline__ void mma_f16(float c[4],
                                        uint32_t a0, uint32_t a1, uint32_t a2, uint32_t a3,
                                        uint32_t b0, uint32_t b1) {
    asm("mma.sync.aligned.m16n8k16.row.col.f32.f16.f16.f32 "
        "{%0,%1,%2,%3}, {%4,%5,%6,%7}, {%8,%9}, {%0,%1,%2,%3};"
        : "+f"(c[0]), "+f"(c[1]), "+f"(c[2]), "+f"(c[3])
        : "r"(a0), "r"(a1), "r"(a2), "r"(a3), "r"(b0), "r"(b1));
}
__device__ __forceinline__ void cp16(uint32_t dst, const void* src) {
    asm volatile("cp.async.cg.shared.global [%0], [%1], 16;"
                 :: "r"(dst), "l"(src) : "memory");
}
__device__ __forceinline__ void cp_commit() {
    asm volatile("cp.async.commit_group;" ::: "memory");
}
__device__ __forceinline__ void cp_wait0() {
    asm volatile("cp.async.wait_group 0;" ::: "memory");
}
__device__ __forceinline__ uint32_t h2_bits(__half2 h) {
    union { __half2 h; uint32_t u; } cvt;
    cvt.h = h;
    return cvt.u;
}
__device__ __forceinline__ float tanh_fast(float x) {   // 1 MUFU, ~5e-4 abs err
    float y;
    asm("tanh.approx.f32 %0, %1;" : "=f"(y) : "f"(x));
    return y;
}

// ---------------------------------------------------------------------------
// fused prep: blocks 0..31 -> hq, blocks 32..159 -> W1 transpose+fp16
// ---------------------------------------------------------------------------
__global__ void prep_kernel(const float* __restrict__ query,
                            const float* __restrict__ W2,
                            const float* __restrict__ W2b,
                            const float* __restrict__ W1) {
    if (blockIdx.x < 32) {
        if (threadIdx.x < UU) {
            int b = blockIdx.x, u = threadIdx.x;
            const float* q = query + b * DD;
            float acc = 0.0f;
#pragma unroll 8
            for (int d = 0; d < DD; d++) acc += q[d] * W2[d * UU + u];
            g_hq[b * UU + u] = fmaxf(acc + W2b[u], 0.0f);
        }
    } else {
        int u = blockIdx.x - 32, d = threadIdx.x;
        g_W1h[u * DD + d] = __float2half_rn(W1[d * UU + u]);
    }
}

// ---------------------------------------------------------------------------
// scores (EXACT R10 best config): fp16 mma, persistent A tile, cp.async
// 4-ring B, fused local softmax + partial context from SMEM fp16.
// 256 threads, 8 warps; warp = (rg 0..3, ch 0..1).
// ---------------------------------------------------------------------------
__global__ __launch_bounds__(256, 2)
void scores_kernel(const float* __restrict__ values,
                   const float* __restrict__ W1b,
                   const float* __restrict__ Vk,
                   const float* __restrict__ Vb) {
    extern __shared__ char smem[];
    const uint32_t sbase = smem_u32(smem);
    const int tid  = threadIdx.x;
    const int wid  = tid >> 5;
    const int lane = tid & 31;
    const int rg   = wid >> 1;
    const int ch   = wid & 1;
    const int mrow = lane & 7;
    const int mi   = lane >> 3;
    const int tg   = lane & 3;
    const int g    = lane >> 2;
    const int row0 = blockIdx.x * MT;
    const int b    = blockIdx.x >> 6;   // 64 tiles per batch

    float* s_sc = (float*)(smem + SC_OFF);
    float* s_es = (float*)(smem + ES_OFF);
    float* s_hq = (float*)(smem + HQ_OFF);
    float* s_b1 = (float*)(smem + B1_OFF);
    float* s_v  = (float*)(smem + VV_OFF);
    float* s_rd = (float*)(smem + RED_OFF);

    if (tid < UU) {
        s_hq[tid] = g_hq[b * UU + tid];
        s_b1[tid] = W1b[tid];
        s_v[tid]  = Vk[tid];
    }

    // ---- B staging via cp.async (fp16, 4-buffer ring) ----
    auto stageB = [&](int c) {
        const uint32_t base = sbase + B_OFF + (c & 3) * 10240;
        const __half* src0 = g_W1h + c * 32;
#pragma unroll
        for (int i = 0; i < 2; i++) {
            int idx = tid + i * 256;         // 512 x 16B = 128 rows x 32 halves
            int u = idx >> 2, kk = idx & 3;
            cp16(base + u * 80 + kk * 16, src0 + u * DD + kk * 8);
        }
    };

    // ---- A staging: LDG fp32 -> regs -> cvt -> STS fp16 into chunk slice ----
    const int ar  = tid >> 3;                // base row handled by this thread
    const int ac4 = tid & 7;                 // float4 column within chunk
    float4 av[4];
    auto ldgA = [&](int c) {
        const float* src0 = values + (size_t)row0 * DD + c * 32 + ac4 * 4;
#pragma unroll
        for (int i = 0; i < 4; i++)
            av[i] = *(const float4*)(src0 + (size_t)(ar + i * 32) * DD);
    };
    auto stsA = [&](int c) {
#pragma unroll
        for (int i = 0; i < 4; i++) {
            __half2 h0 = __floats2half2_rn(av[i].x, av[i].y);
            __half2 h1 = __floats2half2_rn(av[i].z, av[i].w);
            uint2 u2 = make_uint2(h2_bits(h0), h2_bits(h1));
            *(uint2*)(smem + A_OFF + (ar + i * 32) * AROW + c * 64 + ac4 * 8) = u2;
        }
    };

    stageB(0); cp_commit();
    stageB(1); cp_commit();
    stageB(2); cp_commit();
    ldgA(0);
    stsA(0);
    ldgA(1);
    cp_wait0();
    __syncthreads();

    float acc[2][8][4];
#pragma unroll
    for (int m = 0; m < 2; m++)
#pragma unroll
        for (int j = 0; j < 8; j++)
#pragma unroll
            for (int q = 0; q < 4; q++) acc[m][j][q] = 0.0f;

    // fragment address components
    const int a_r  = 32 * rg + mrow + 8 * (mi & 1);
    const int a_kb = (mi >> 1) * 16;
    const int b_n  = 64 * ch + mrow + 8 * (mi >> 1);
    const int b_kb = (mi & 1) * 16;

    for (int c = 0; c < 8; c++) {
        const uint32_t abase = sbase + A_OFF + c * 64;
        const uint32_t bbase = sbase + B_OFF + (c & 3) * 10240;
#pragma unroll
        for (int ks = 0; ks < 2; ks++) {
            const int k0 = ks * 32;          // bytes within 64B chunk slice
            uint32_t a0[4], a1[4];
            ldsm4(a0, abase + (a_r)      * AROW + a_kb + k0);
            ldsm4(a1, abase + (a_r + 16) * AROW + a_kb + k0);
#pragma unroll
            for (int nt = 0; nt < 4; nt++) {
                uint32_t bq[4];
                ldsm4(bq, bbase + (b_n + 16 * nt) * 80 + b_kb + k0);
                mma_f16(acc[0][2 * nt],     a0[0], a0[1], a0[2], a0[3], bq[0], bq[1]);
                mma_f16(acc[0][2 * nt + 1], a0[0], a0[1], a0[2], a0[3], bq[2], bq[3]);
                mma_f16(acc[1][2 * nt],     a1[0], a1[1], a1[2], a1[3], bq[0], bq[1]);
                mma_f16(acc[1][2 * nt + 1], a1[0], a1[1], a1[2], a1[3], bq[2], bq[3]);
            }
        }
        if (c + 1 < 8) stsA(c + 1);
        if (c + 2 < 8) ldgA(c + 2);
        if (c + 3 < 8) stageB(c + 3);
        cp_commit();
        cp_wait0();
        __syncthreads();
    }

    // ---- epilogue 1: per-row score partials (this warp's 64-col half) ----
    float s[4] = {0.f, 0.f, 0.f, 0.f};
#pragma unroll
    for (int j = 0; j < 8; j++) {
        const int u0 = 64 * ch + 8 * j + 2 * tg;
        const int u1 = u0 + 1;
        const float v0 = s_v[u0], v1 = s_v[u1];
        const float h0 = s_hq[u0], h1 = s_hq[u1];
        const float c0 = s_b1[u0], c1 = s_b1[u1];
#pragma unroll
        for (int m = 0; m < 2; m++) {
            s[2 * m]     += v0 * tanh_fast(fmaxf(acc[m][j][0] + c0, 0.f) + h0)
                          + v1 * tanh_fast(fmaxf(acc[m][j][1] + c1, 0.f) + h1);
            s[2 * m + 1] += v0 * tanh_fast(fmaxf(acc[m][j][2] + c0, 0.f) + h0)
                          + v1 * tanh_fast(fmaxf(acc[m][j][3] + c1, 0.f) + h1);
        }
    }
#pragma unroll
    for (int i = 0; i < 4; i++) {
        s[i] += __shfl_xor_sync(0xffffffffu, s[i], 1);
        s[i] += __shfl_xor_sync(0xffffffffu, s[i], 2);
    }
    if (tg == 0) {
        const int rb = 32 * rg + g;
        s_sc[ch * 128 + rb]      = s[0];
        s_sc[ch * 128 + rb + 8]  = s[1];
        s_sc[ch * 128 + rb + 16] = s[2];
        s_sc[ch * 128 + rb + 24] = s[3];
    }
    __syncthreads();

    // ---- epilogue 2: combine halves, local max / exp / sum ----
    float myv = -3.0e38f;
    if (tid < 128) {
        myv = s_sc[tid] + s_sc[128 + tid] + Vb[0];
        g_scores[row0 + tid] = myv;
    }
    float m = myv;
#pragma unroll
    for (int o = 16; o > 0; o >>= 1) m = fmaxf(m, __shfl_xor_sync(0xffffffffu, m, o));
    if (lane == 0 && wid < 4) s_rd[wid] = m;
    __syncthreads();
    if (tid == 0) {
        s_rd[32] = fmaxf(fmaxf(s_rd[0], s_rd[1]), fmaxf(s_rd[2], s_rd[3]));
    }
    __syncthreads();
    const float mloc = s_rd[32];
    float e = (tid < 128) ? __expf(myv - mloc) : 0.0f;
    if (tid < 128) s_es[tid] = e;
    float sum = e;
#pragma unroll
    for (int o = 16; o > 0; o >>= 1) sum += __shfl_xor_sync(0xffffffffu, sum, o);
    if (lane == 0 && wid < 4) s_rd[8 + wid] = sum;
    __syncthreads();
    if (tid == 0) {
        g_stats[blockIdx.x * 2]     = mloc;
        g_stats[blockIdx.x * 2 + 1] = s_rd[8] + s_rd[9] + s_rd[10] + s_rd[11];
    }

    // ---- epilogue 3: partial context from the persistent SMEM fp16 A tile ----
    {
        float a = 0.0f;
#pragma unroll 8
        for (int r = 0; r < MT; r++) {
            __half hv = *(const __half*)(smem + A_OFF + r * AROW + tid * 2);
            a += s_es[r] * __half2float(hv);
        }
        g_pctx[blockIdx.x * DD + tid] = a;
    }
}

// ---------------------------------------------------------------------------
// fused tail: 256 blocks = 8 per batch, 256 threads.
// Every block recomputes (M, 1/S) for its batch from g_stats (no dependency).
// Sub-block 0 writes the context reduction; all 8 write 1/8 of the weights.
// ---------------------------------------------------------------------------
__global__ void tail_kernel(float* __restrict__ ctx, float* __restrict__ wts) {
    __shared__ float coef[64], red[8];
    const int b   = blockIdx.x >> 3;
    const int sub = blockIdx.x & 7;
    const int tid = threadIdx.x, lane = tid & 31, w = tid >> 5;

    float val = 0.0f, cs = 0.0f;
    float m = -3.0e38f;
    if (tid < 64) {
        val = g_stats[(b * 64 + tid) * 2];
        cs  = g_stats[(b * 64 + tid) * 2 + 1];
        m = val;
    }
#pragma unroll
    for (int o = 16; o > 0; o >>= 1) m = fmaxf(m, __shfl_xor_sync(0xffffffffu, m, o));
    if (tid < 64 && lane == 0) red[w] = m;
    __syncthreads();
    if (tid == 0) red[2] = fmaxf(red[0], red[1]);
    __syncthreads();
    const float M = red[2];
    float c = 0.0f;
    if (tid < 64) {
        c = __expf(val - M);
        coef[tid] = c;
        c *= cs;
    }
#pragma unroll
    for (int o = 16; o > 0; o >>= 1) c += __shfl_xor_sync(0xffffffffu, c, o);
    if (tid < 64 && lane == 0) red[4 + w] = c;
    __syncthreads();
    if (tid == 0) red[6] = 1.0f / (red[4] + red[5]);
    __syncthreads();
    const float inv = red[6];

    // context reduction (sub-block 0 only)
    if (sub == 0) {
        float acc = 0.0f;
#pragma unroll
        for (int k = 0; k < 64; k++) acc += coef[k] * g_pctx[(b * 64 + k) * DD + tid];
        ctx[b * DD + tid] = acc * inv;
    }

    // normalized weights: this block's 256 float4 slice of batch b
    {
        int i = b * 2048 + sub * 256 + tid;      // float4 index
        float4 sc = ((const float4*)g_scores)[i];
        float4 o;
        o.x = __expf(sc.x - M) * inv;
        o.y = __expf(sc.y - M) * inv;
        o.z = __expf(sc.z - M) * inv;
        o.w = __expf(sc.w - M) * inv;
        ((float4*)wts)[i] = o;
    }
}

// ---------------------------------------------------------------------------
extern "C" void kernel_launch(void* const* d_in, const int* in_sizes, int n_in,
                              void* d_out, int out_size) {
    const float* query  = (const float*)d_in[0];
    const float* values = (const float*)d_in[1];
    const float* W1     = (const float*)d_in[2];
    const float* W1b    = (const float*)d_in[3];
    const float* W2     = (const float*)d_in[4];
    const float* W2b    = (const float*)d_in[5];
    const float* Vk     = (const float*)d_in[6];
    const float* Vb     = (const float*)d_in[7];

    float* out = (float*)d_out;
    float* ctx = out;               // [B, D]
    float* wts = out + BB * DD;     // [B, T, 1]

    static bool attr_set = false;
    if (!attr_set) {
        cudaFuncSetAttribute(scores_kernel, cudaFuncAttributeMaxDynamicSharedMemorySize,
                             SMEM_BYTES);
        attr_set = true;
    }

    prep_kernel<<<160, 256>>>(query, W2, W2b, W1);
    scores_kernel<<<NCTA, 256, SMEM_BYTES>>>(values, W1b, Vk, Vb);
    tail_kernel<<<256, 256>>>(ctx, wts);
}

// round 17
// speedup vs baseline: 1.1143x; 1.0270x over previous
#include <cuda_runtime.h>
#include <cuda_fp16.h>
#include <cstdint>

#define BB 32
#define TT 8192
#define DD 256
#define UU 128
#define MT 128
#define NCTA ((BB * TT) / MT)   // 2048 tiles, 64 per batch

#define AROW 528                 // A row stride BYTES: 512 payload + 16 pad
// ---- dynamic SMEM layout (bytes) ----
#define A_OFF   0                // 128 rows x 528B = 67584 (full fp16 tile)
#define B_OFF   67584            // 4 x (128 rows x 80B) = 40960
#define SC_OFF  108544           // [2][128] floats = 1024
#define ES_OFF  109568           // 128 floats
#define HQ_OFF  110080           // 128 floats
#define B1_OFF  110592           // 128 floats
#define VV_OFF  111104           // 128 floats
#define RED_OFF 111616           // 64 floats
#define SMEM_BYTES 112128

// ---- scratch globals (allocation-free) ----
__device__ float  g_hq[BB * UU];
__device__ __half g_W1h[UU * DD];       // W1 transposed -> [u][d], fp16
__device__ float  g_scores[BB * TT];
__device__ float  g_stats[NCTA * 2];    // per-tile (local max, local expsum)
__device__ float  g_pctx[NCTA * DD];    // per-tile unnormalized partial context

// ---------------------------------------------------------------------------
// helpers
// ---------------------------------------------------------------------------
__device__ __forceinline__ uint32_t smem_u32(const void* p) {
    uint32_t a;
    asm("{ .reg .u64 t; cvta.to.shared.u64 t, %1; cvt.u32.u64 %0, t; }" : "=r"(a) : "l"(p));
    return a;
}
__device__ __forceinline__ void ldsm4(uint32_t (&r)[4], uint32_t addr) {
    asm volatile("ldmatrix.sync.aligned.m8n8.x4.shared.b16 {%0,%1,%2,%3}, [%4];"
                 : "=r"(r[0]), "=r"(r[1]), "=r"(r[2]), "=r"(r[3]) : "r"(addr));
}
__device__ __forceinline__ void mma_f16(float c[4],
                                        uint32_t a0, uint32_t a1, uint32_t a2, uint32_t a3,
                                        uint32_t b0, uint32_t b1) {
    asm("mma.sync.aligned.m16n8k16.row.col.f32.f16.f16.f32 "
        "{%0,%1,%2,%3}, {%4,%5,%6,%7}, {%8,%9}, {%0,%1,%2,%3};"
        : "+f"(c[0]), "+f"(c[1]), "+f"(c[2]), "+f"(c[3])
        : "r"(a0), "r"(a1), "r"(a2), "r"(a3), "r"(b0), "r"(b1));
}
__device__ __forceinline__ void cp16(uint32_t dst, const void* src) {
    asm volatile("cp.async.cg.shared.global [%0], [%1], 16;"
                 :: "r"(dst), "l"(src) : "memory");
}
__device__ __forceinline__ void cp_commit() {
    asm volatile("cp.async.commit_group;" ::: "memory");
}
__device__ __forceinline__ void cp_wait0() {
    asm volatile("cp.async.wait_group 0;" ::: "memory");
}
__device__ __forceinline__ uint32_t h2_bits(__half2 h) {
    union { __half2 h; uint32_t u; } cvt;
    cvt.h = h;
    return cvt.u;
}
__device__ __forceinline__ float tanh_fast(float x) {   // 1 MUFU, ~5e-4 abs err
    float y;
    asm("tanh.approx.f32 %0, %1;" : "=f"(y) : "f"(x));
    return y;
}

// ---------------------------------------------------------------------------
// prep: blocks 0..31 -> hq (4-acc ILP, float4 loads);
//       blocks 32..95 -> W1 transpose with COALESCED reads, posted writes.
// ---------------------------------------------------------------------------
__global__ void prep_kernel(const float* __restrict__ query,
                            const float* __restrict__ W2,
                            const float* __restrict__ W2b,
                            const float* __restrict__ W1) {
    if (blockIdx.x < 32) {
        if (threadIdx.x < UU) {
            const int b = blockIdx.x, u = threadIdx.x;
            const float* q = query + b * DD;
            float a0 = 0.f, a1 = 0.f, a2 = 0.f, a3 = 0.f;
#pragma unroll
            for (int d = 0; d < DD; d += 4) {
                a0 += q[d]     * W2[d * UU + u];
                a1 += q[d + 1] * W2[(d + 1) * UU + u];
                a2 += q[d + 2] * W2[(d + 2) * UU + u];
                a3 += q[d + 3] * W2[(d + 3) * UU + u];
            }
            g_hq[b * UU + u] = fmaxf((a0 + a1) + (a2 + a3) + W2b[u], 0.0f);
        }
    } else {
        // 64 blocks x 256 threads; each block converts 4 d-rows of W1.
        // Read W1[d][u] coalesced (warp sweeps u); write g_W1h[u][d] scattered
        // (posted stores, no stall).
        const int blk = blockIdx.x - 32;
        const int u = threadIdx.x & 127;
        const int dh = threadIdx.x >> 7;          // 0..1
#pragma unroll
        for (int it = 0; it < 2; it++) {
            const int d = blk * 4 + it * 2 + dh;
            g_W1h[u * DD + d] = __float2half_rn(W1[d * UU + u]);
        }
    }
}

// ---------------------------------------------------------------------------
// scores (EXACT R10 best config): fp16 mma, persistent A tile, cp.async
// 4-ring B, fused local softmax + partial context from SMEM fp16.
// 256 threads, 8 warps; warp = (rg 0..3, ch 0..1).
// ---------------------------------------------------------------------------
__global__ __launch_bounds__(256, 2)
void scores_kernel(const float* __restrict__ values,
                   const float* __restrict__ W1b,
                   const float* __restrict__ Vk,
                   const float* __restrict__ Vb) {
    extern __shared__ char smem[];
    const uint32_t sbase = smem_u32(smem);
    const int tid  = threadIdx.x;
    const int wid  = tid >> 5;
    const int lane = tid & 31;
    const int rg   = wid >> 1;
    const int ch   = wid & 1;
    const int mrow = lane & 7;
    const int mi   = lane >> 3;
    const int tg   = lane & 3;
    const int g    = lane >> 2;
    const int row0 = blockIdx.x * MT;
    const int b    = blockIdx.x >> 6;   // 64 tiles per batch

    float* s_sc = (float*)(smem + SC_OFF);
    float* s_es = (float*)(smem + ES_OFF);
    float* s_hq = (float*)(smem + HQ_OFF);
    float* s_b1 = (float*)(smem + B1_OFF);
    float* s_v  = (float*)(smem + VV_OFF);
    float* s_rd = (float*)(smem + RED_OFF);

    if (tid < UU) {
        s_hq[tid] = g_hq[b * UU + tid];
        s_b1[tid] = W1b[tid];
        s_v[tid]  = Vk[tid];
    }

    // ---- B staging via cp.async (fp16, 4-buffer ring) ----
    auto stageB = [&](int c) {
        const uint32_t base = sbase + B_OFF + (c & 3) * 10240;
        const __half* src0 = g_W1h + c * 32;
#pragma unroll
        for (int i = 0; i < 2; i++) {
            int idx = tid + i * 256;         // 512 x 16B = 128 rows x 32 halves
            int u = idx >> 2, kk = idx & 3;
            cp16(base + u * 80 + kk * 16, src0 + u * DD + kk * 8);
        }
    };

    // ---- A staging: LDG fp32 -> regs -> cvt -> STS fp16 into chunk slice ----
    const int ar  = tid >> 3;                // base row handled by this thread
    const int ac4 = tid & 7;                 // float4 column within chunk
    float4 av[4];
    auto ldgA = [&](int c) {
        const float* src0 = values + (size_t)row0 * DD + c * 32 + ac4 * 4;
#pragma unroll
        for (int i = 0; i < 4; i++)
            av[i] = *(const float4*)(src0 + (size_t)(ar + i * 32) * DD);
    };
    auto stsA = [&](int c) {
#pragma unroll
        for (int i = 0; i < 4; i++) {
            __half2 h0 = __floats2half2_rn(av[i].x, av[i].y);
            __half2 h1 = __floats2half2_rn(av[i].z, av[i].w);
            uint2 u2 = make_uint2(h2_bits(h0), h2_bits(h1));
            *(uint2*)(smem + A_OFF + (ar + i * 32) * AROW + c * 64 + ac4 * 8) = u2;
        }
    };

    stageB(0); cp_commit();
    stageB(1); cp_commit();
    stageB(2); cp_commit();
    ldgA(0);
    stsA(0);
    ldgA(1);
    cp_wait0();
    __syncthreads();

    float acc[2][8][4];
#pragma unroll
    for (int m = 0; m < 2; m++)
#pragma unroll
        for (int j = 0; j < 8; j++)
#pragma unroll
            for (int q = 0; q < 4; q++) acc[m][j][q] = 0.0f;

    // fragment address components
    const int a_r  = 32 * rg + mrow + 8 * (mi & 1);
    const int a_kb = (mi >> 1) * 16;
    const int b_n  = 64 * ch + mrow + 8 * (mi >> 1);
    const int b_kb = (mi & 1) * 16;

    for (int c = 0; c < 8; c++) {
        const uint32_t abase = sbase + A_OFF + c * 64;
        const uint32_t bbase = sbase + B_OFF + (c & 3) * 10240;
#pragma unroll
        for (int ks = 0; ks < 2; ks++) {
            const int k0 = ks * 32;          // bytes within 64B chunk slice
            uint32_t a0[4], a1[4];
            ldsm4(a0, abase + (a_r)      * AROW + a_kb + k0);
            ldsm4(a1, abase + (a_r + 16) * AROW + a_kb + k0);
#pragma unroll
            for (int nt = 0; nt < 4; nt++) {
                uint32_t bq[4];
                ldsm4(bq, bbase + (b_n + 16 * nt) * 80 + b_kb + k0);
                mma_f16(acc[0][2 * nt],     a0[0], a0[1], a0[2], a0[3], bq[0], bq[1]);
                mma_f16(acc[0][2 * nt + 1], a0[0], a0[1], a0[2], a0[3], bq[2], bq[3]);
                mma_f16(acc[1][2 * nt],     a1[0], a1[1], a1[2], a1[3], bq[0], bq[1]);
                mma_f16(acc[1][2 * nt + 1], a1[0], a1[1], a1[2], a1[3], bq[2], bq[3]);
            }
        }
        if (c + 1 < 8) stsA(c + 1);
        if (c + 2 < 8) ldgA(c + 2);
        if (c + 3 < 8) stageB(c + 3);
        cp_commit();
        cp_wait0();
        __syncthreads();
    }

    // ---- epilogue 1: per-row score partials (this warp's 64-col half) ----
    float s[4] = {0.f, 0.f, 0.f, 0.f};
#pragma unroll
    for (int j = 0; j < 8; j++) {
        const int u0 = 64 * ch + 8 * j + 2 * tg;
        const int u1 = u0 + 1;
        const float v0 = s_v[u0], v1 = s_v[u1];
        const float h0 = s_hq[u0], h1 = s_hq[u1];
        const float c0 = s_b1[u0], c1 = s_b1[u1];
#pragma unroll
        for (int m = 0; m < 2; m++) {
            s[2 * m]     += v0 * tanh_fast(fmaxf(acc[m][j][0] + c0, 0.f) + h0)
                          + v1 * tanh_fast(fmaxf(acc[m][j][1] + c1, 0.f) + h1);
            s[2 * m + 1] += v0 * tanh_fast(fmaxf(acc[m][j][2] + c0, 0.f) + h0)
                          + v1 * tanh_fast(fmaxf(acc[m][j][3] + c1, 0.f) + h1);
        }
    }
#pragma unroll
    for (int i = 0; i < 4; i++) {
        s[i] += __shfl_xor_sync(0xffffffffu, s[i], 1);
        s[i] += __shfl_xor_sync(0xffffffffu, s[i], 2);
    }
    if (tg == 0) {
        const int rb = 32 * rg + g;
        s_sc[ch * 128 + rb]      = s[0];
        s_sc[ch * 128 + rb + 8]  = s[1];
        s_sc[ch * 128 + rb + 16] = s[2];
        s_sc[ch * 128 + rb + 24] = s[3];
    }
    __syncthreads();

    // ---- epilogue 2: combine halves, local max / exp / sum ----
    float myv = -3.0e38f;
    if (tid < 128) {
        myv = s_sc[tid] + s_sc[128 + tid] + Vb[0];
        g_scores[row0 + tid] = myv;
    }
    float m = myv;
#pragma unroll
    for (int o = 16; o > 0; o >>= 1) m = fmaxf(m, __shfl_xor_sync(0xffffffffu, m, o));
    if (lane == 0 && wid < 4) s_rd[wid] = m;
    __syncthreads();
    if (tid == 0) {
        s_rd[32] = fmaxf(fmaxf(s_rd[0], s_rd[1]), fmaxf(s_rd[2], s_rd[3]));
    }
    __syncthreads();
    const float mloc = s_rd[32];
    float e = (tid < 128) ? __expf(myv - mloc) : 0.0f;
    if (tid < 128) s_es[tid] = e;
    float sum = e;
#pragma unroll
    for (int o = 16; o > 0; o >>= 1) sum += __shfl_xor_sync(0xffffffffu, sum, o);
    if (lane == 0 && wid < 4) s_rd[8 + wid] = sum;
    __syncthreads();
    if (tid == 0) {
        g_stats[blockIdx.x * 2]     = mloc;
        g_stats[blockIdx.x * 2 + 1] = s_rd[8] + s_rd[9] + s_rd[10] + s_rd[11];
    }

    // ---- epilogue 3: partial context from the persistent SMEM fp16 A tile ----
    {
        float a = 0.0f;
#pragma unroll 8
        for (int r = 0; r < MT; r++) {
            __half hv = *(const __half*)(smem + A_OFF + r * AROW + tid * 2);
            a += s_es[r] * __half2float(hv);
        }
        g_pctx[blockIdx.x * DD + tid] = a;
    }
}

// ---------------------------------------------------------------------------
// fused tail: 256 blocks = 8 per batch, 256 threads.
// Every block recomputes (M, 1/S) for its batch from g_stats (no dependency).
// Sub-block 0 writes the context reduction; all 8 write 1/8 of the weights.
// ---------------------------------------------------------------------------
__global__ void tail_kernel(float* __restrict__ ctx, float* __restrict__ wts) {
    __shared__ float coef[64], red[8];
    const int b   = blockIdx.x >> 3;
    const int sub = blockIdx.x & 7;
    const int tid = threadIdx.x, lane = tid & 31, w = tid >> 5;

    float val = 0.0f, cs = 0.0f;
    float m = -3.0e38f;
    if (tid < 64) {
        val = g_stats[(b * 64 + tid) * 2];
        cs  = g_stats[(b * 64 + tid) * 2 + 1];
        m = val;
    }
#pragma unroll
    for (int o = 16; o > 0; o >>= 1) m = fmaxf(m, __shfl_xor_sync(0xffffffffu, m, o));
    if (tid < 64 && lane == 0) red[w] = m;
    __syncthreads();
    if (tid == 0) red[2] = fmaxf(red[0], red[1]);
    __syncthreads();
    const float M = red[2];
    float c = 0.0f;
    if (tid < 64) {
        c = __expf(val - M);
        coef[tid] = c;
        c *= cs;
    }
#pragma unroll
    for (int o = 16; o > 0; o >>= 1) c += __shfl_xor_sync(0xffffffffu, c, o);
    if (tid < 64 && lane == 0) red[4 + w] = c;
    __syncthreads();
    if (tid == 0) red[6] = 1.0f / (red[4] + red[5]);
    __syncthreads();
    const float inv = red[6];

    // context reduction (sub-block 0 only)
    if (sub == 0) {
        float acc = 0.0f;
#pragma unroll
        for (int k = 0; k < 64; k++) acc += coef[k] * g_pctx[(b * 64 + k) * DD + tid];
        ctx[b * DD + tid] = acc * inv;
    }

    // normalized weights: this block's 256 float4 slice of batch b
    {
        int i = b * 2048 + sub * 256 + tid;      // float4 index
        float4 sc = ((const float4*)g_scores)[i];
        float4 o;
        o.x = __expf(sc.x - M) * inv;
        o.y = __expf(sc.y - M) * inv;
        o.z = __expf(sc.z - M) * inv;
        o.w = __expf(sc.w - M) * inv;
        ((float4*)wts)[i] = o;
    }
}

// ---------------------------------------------------------------------------
extern "C" void kernel_launch(void* const* d_in, const int* in_sizes, int n_in,
                              void* d_out, int out_size) {
    const float* query  = (const float*)d_in[0];
    const float* values = (const float*)d_in[1];
    const float* W1     = (const float*)d_in[2];
    const float* W1b    = (const float*)d_in[3];
    const float* W2     = (const float*)d_in[4];
    const float* W2b    = (const float*)d_in[5];
    const float* Vk     = (const float*)d_in[6];
    const float* Vb     = (const float*)d_in[7];

    float* out = (float*)d_out;
    float* ctx = out;               // [B, D]
    float* wts = out + BB * DD;     // [B, T, 1]

    static bool attr_set = false;
    if (!attr_set) {
        cudaFuncSetAttribute(scores_kernel, cudaFuncAttributeMaxDynamicSharedMemorySize,
                             SMEM_BYTES);
        attr_set = true;
    }

    prep_kernel<<<96, 256>>>(query, W2, W2b, W1);
    scores_kernel<<<NCTA, 256, SMEM_BYTES>>>(values, W1b, Vk, Vb);
    tail_kernel<<<256, 256>>>(ctx, wts);
}